// round 1
// baseline (speedup 1.0000x reference)
#include <cuda_runtime.h>

#define SEQ    4096
#define DMODEL 1024
#define HEADS  16
#define DHEAD  64

// Scratch (no cudaMalloc allowed): Q,K,V projections and attention output.
__device__ float g_q[SEQ * DMODEL];
__device__ float g_k[SEQ * DMODEL];
__device__ float g_v[SEQ * DMODEL];
__device__ float g_at[SEQ * DMODEL];

// ---------------------------------------------------------------------------
// Generic tiled SGEMM: C = A[M,K] @ B[K,N] (+bias). BM=BN=64, BK=16,
// 256 threads, 4x4 micro-tile per thread. blockIdx.z selects (B,C) pair so
// the QKV projections run as one fused launch.
// ---------------------------------------------------------------------------
__global__ void __launch_bounds__(256) gemm64(
    const float* __restrict__ A,
    const float* __restrict__ B0, const float* __restrict__ B1,
    const float* __restrict__ B2,
    const float* __restrict__ bias,
    float* __restrict__ C0, float* __restrict__ C1, float* __restrict__ C2,
    int M, int N, int K)
{
    const float* B = (blockIdx.z == 0) ? B0 : (blockIdx.z == 1 ? B1 : B2);
    float*       C = (blockIdx.z == 0) ? C0 : (blockIdx.z == 1 ? C1 : C2);

    __shared__ float As[64][16];
    __shared__ float Bs[16][64];

    const int tid = threadIdx.x;
    const int bm = blockIdx.y * 64;
    const int bn = blockIdx.x * 64;
    const int tx = tid & 15, ty = tid >> 4;
    const int r0 = ty * 4, c0 = tx * 4;

    // Load mapping: A tile 64x16 (float4 along K), B tile 16x64 (float4 along N)
    const int a_row = tid >> 2;
    const int a_col = (tid & 3) * 4;
    const int b_row = tid >> 4;
    const int b_col = (tid & 15) * 4;

    const float* Ag = A + (size_t)(bm + a_row) * K + a_col;
    const float* Bg = B + (size_t)b_row * N + bn + b_col;

    float acc[4][4] = {};

    for (int k0 = 0; k0 < K; k0 += 16) {
        float4 av = *reinterpret_cast<const float4*>(Ag + k0);
        float4 bv = *reinterpret_cast<const float4*>(Bg + (size_t)k0 * N);
        *reinterpret_cast<float4*>(&As[a_row][a_col]) = av;
        *reinterpret_cast<float4*>(&Bs[b_row][b_col]) = bv;
        __syncthreads();
#pragma unroll
        for (int kk = 0; kk < 16; kk++) {
            float a0 = As[r0 + 0][kk];
            float a1 = As[r0 + 1][kk];
            float a2 = As[r0 + 2][kk];
            float a3 = As[r0 + 3][kk];
            float4 b = *reinterpret_cast<const float4*>(&Bs[kk][c0]);
            acc[0][0] += a0 * b.x; acc[0][1] += a0 * b.y; acc[0][2] += a0 * b.z; acc[0][3] += a0 * b.w;
            acc[1][0] += a1 * b.x; acc[1][1] += a1 * b.y; acc[1][2] += a1 * b.z; acc[1][3] += a1 * b.w;
            acc[2][0] += a2 * b.x; acc[2][1] += a2 * b.y; acc[2][2] += a2 * b.z; acc[2][3] += a2 * b.w;
            acc[3][0] += a3 * b.x; acc[3][1] += a3 * b.y; acc[3][2] += a3 * b.z; acc[3][3] += a3 * b.w;
        }
        __syncthreads();
    }

    float4 bb = make_float4(0.f, 0.f, 0.f, 0.f);
    if (bias) bb = *reinterpret_cast<const float4*>(&bias[bn + c0]);
#pragma unroll
    for (int i = 0; i < 4; i++) {
        float4 o = make_float4(acc[i][0] + bb.x, acc[i][1] + bb.y,
                               acc[i][2] + bb.z, acc[i][3] + bb.w);
        *reinterpret_cast<float4*>(&C[(size_t)(bm + r0 + i) * N + bn + c0]) = o;
    }
}

// ---------------------------------------------------------------------------
// Flash attention, fp32, causal. One CTA = (64-row block, head).
// S is computed TRANSPOSED (S^T = K @ Q^T) so K and V stay in natural
// [key][d] layout and P lands key-major, which is exactly what the PV
// outer-product wants. Online softmax with running (m, l).
// Dynamic smem: Qt[64][64] + Ks[64][64] + Vs[64][64] + Ss[64][68] + m/l/sc.
// ---------------------------------------------------------------------------
#define ATTN_SMEM_FLOATS (4096 * 3 + 64 * 68 + 192)
#define ATTN_SMEM_BYTES  (ATTN_SMEM_FLOATS * 4)

__global__ void __launch_bounds__(256) attn_kernel(
    const float* __restrict__ qg, const float* __restrict__ kg,
    const float* __restrict__ vg, float* __restrict__ outg)
{
    extern __shared__ float sm[];
    float* Qt   = sm;                 // [d][row]   4096
    float* Ks   = sm + 4096;          // [key][d]   4096
    float* Vs   = sm + 8192;          // [key][d]   4096
    float* Ss   = sm + 12288;         // [key][row] 64*68 (pitch 68)
    float* m_s  = sm + 12288 + 4352;  // 64
    float* l_s  = m_s + 64;           // 64
    float* sc_s = l_s + 64;           // 64

    const int tid  = threadIdx.x;
    const int h    = blockIdx.y;
    const int ib   = (int)(gridDim.x - 1u - blockIdx.x);  // heavy blocks first
    const int row0 = ib * 64;
    const int hoff = h * DHEAD;
    const float beta = 0.125f;  // 1/sqrt(64)

    const int tx = tid & 15, ty = tid >> 4;
    // S^T mapping: key tile rows kq0 (from ty), query rows rq0 (from tx)
    const int kq0 = ty * 4;
    const int rq0 = tx * 4;
    // O mapping: rows r0o (from ty), head-dim cols c0o (from tx)
    const int r0o = ty * 4;
    const int c0o = tx * 4;

    // -------- load Q tile, transposed, pre-scaled by beta --------
    {
        const int r = tid >> 2;              // 0..63
        const int dbase = (tid & 3) * 16;    // 0,16,32,48
        const float* qp = qg + (size_t)(row0 + r) * DMODEL + hoff + dbase;
#pragma unroll
        for (int u = 0; u < 4; u++) {
            float4 qv = *reinterpret_cast<const float4*>(qp + 4 * u);
            Qt[(dbase + 4 * u + 0) * 64 + r] = qv.x * beta;
            Qt[(dbase + 4 * u + 1) * 64 + r] = qv.y * beta;
            Qt[(dbase + 4 * u + 2) * 64 + r] = qv.z * beta;
            Qt[(dbase + 4 * u + 3) * 64 + r] = qv.w * beta;
        }
    }
    if (tid < 64) { m_s[tid] = -1e30f; l_s[tid] = 0.f; }

    float o[4][4] = {};

    for (int jb = 0; jb <= ib; jb++) {
        __syncthreads();   // prev-iter consumers done; Q/m/l visible on iter 0
        // -------- load K, V tiles (natural [key][d] layout) --------
        {
            const int kv = tid >> 2;
            const int dbase = (tid & 3) * 16;
            const float* kp = kg + (size_t)(jb * 64 + kv) * DMODEL + hoff + dbase;
            const float* vp = vg + (size_t)(jb * 64 + kv) * DMODEL + hoff + dbase;
#pragma unroll
            for (int u = 0; u < 4; u++) {
                *reinterpret_cast<float4*>(&Ks[kv * 64 + dbase + 4 * u]) =
                    *reinterpret_cast<const float4*>(kp + 4 * u);
                *reinterpret_cast<float4*>(&Vs[kv * 64 + dbase + 4 * u]) =
                    *reinterpret_cast<const float4*>(vp + 4 * u);
            }
        }
        __syncthreads();

        // -------- S^T[key][row] = K @ Q^T --------
        float s[4][4] = {};
#pragma unroll 16
        for (int kk = 0; kk < 64; kk++) {
            float a0 = Ks[(kq0 + 0) * 64 + kk];
            float a1 = Ks[(kq0 + 1) * 64 + kk];
            float a2 = Ks[(kq0 + 2) * 64 + kk];
            float a3 = Ks[(kq0 + 3) * 64 + kk];
            float4 b = *reinterpret_cast<const float4*>(&Qt[kk * 64 + rq0]);
            s[0][0] += a0 * b.x; s[0][1] += a0 * b.y; s[0][2] += a0 * b.z; s[0][3] += a0 * b.w;
            s[1][0] += a1 * b.x; s[1][1] += a1 * b.y; s[1][2] += a1 * b.z; s[1][3] += a1 * b.w;
            s[2][0] += a2 * b.x; s[2][1] += a2 * b.y; s[2][2] += a2 * b.z; s[2][3] += a2 * b.w;
            s[3][0] += a3 * b.x; s[3][1] += a3 * b.y; s[3][2] += a3 * b.z; s[3][3] += a3 * b.w;
        }
        if (jb == ib) {  // causal mask on the diagonal tile: key > row -> -inf
#pragma unroll
            for (int i = 0; i < 4; i++)
#pragma unroll
                for (int j = 0; j < 4; j++)
                    if (kq0 + i > rq0 + j) s[i][j] = -1e30f;
        }
#pragma unroll
        for (int i = 0; i < 4; i++)
            *reinterpret_cast<float4*>(&Ss[(kq0 + i) * 68 + rq0]) =
                make_float4(s[i][0], s[i][1], s[i][2], s[i][3]);
        __syncthreads();

        // -------- online softmax over key axis (4 threads per row) --------
        {
            const int row = tid >> 2, sub = tid & 3;
            float mx = -1e30f;
#pragma unroll
            for (int t = 0; t < 16; t++) {
                int kk = t * 4 + sub;  // stride-4: distinct banks per sub
                mx = fmaxf(mx, Ss[kk * 68 + row]);
            }
            mx = fmaxf(mx, __shfl_xor_sync(0xffffffffu, mx, 1));
            mx = fmaxf(mx, __shfl_xor_sync(0xffffffffu, mx, 2));
            float mold = m_s[row];
            float mnew = fmaxf(mold, mx);
            float sum = 0.f;
#pragma unroll
            for (int t = 0; t < 16; t++) {
                int kk = t * 4 + sub;
                float p = __expf(Ss[kk * 68 + row] - mnew);
                Ss[kk * 68 + row] = p;
                sum += p;
            }
            sum += __shfl_xor_sync(0xffffffffu, sum, 1);
            sum += __shfl_xor_sync(0xffffffffu, sum, 2);
            if (sub == 0) {
                float sc = __expf(mold - mnew);
                sc_s[row] = sc;
                l_s[row] = l_s[row] * sc + sum;
                m_s[row] = mnew;
            }
        }
        __syncthreads();

        // -------- rescale O, accumulate O += P^T-as-stored @ V --------
        {
            float s0 = sc_s[r0o + 0], s1 = sc_s[r0o + 1],
                  s2 = sc_s[r0o + 2], s3 = sc_s[r0o + 3];
#pragma unroll
            for (int j = 0; j < 4; j++) {
                o[0][j] *= s0; o[1][j] *= s1; o[2][j] *= s2; o[3][j] *= s3;
            }
        }
#pragma unroll 16
        for (int kk = 0; kk < 64; kk++) {
            float4 a = *reinterpret_cast<const float4*>(&Ss[kk * 68 + r0o]);
            float4 b = *reinterpret_cast<const float4*>(&Vs[kk * 64 + c0o]);
            o[0][0] += a.x * b.x; o[0][1] += a.x * b.y; o[0][2] += a.x * b.z; o[0][3] += a.x * b.w;
            o[1][0] += a.y * b.x; o[1][1] += a.y * b.y; o[1][2] += a.y * b.z; o[1][3] += a.y * b.w;
            o[2][0] += a.z * b.x; o[2][1] += a.z * b.y; o[2][2] += a.z * b.z; o[2][3] += a.z * b.w;
            o[3][0] += a.w * b.x; o[3][1] += a.w * b.y; o[3][2] += a.w * b.z; o[3][3] += a.w * b.w;
        }
    }

    __syncthreads();
#pragma unroll
    for (int i = 0; i < 4; i++) {
        float inv = 1.0f / l_s[r0o + i];
        float4 ov = make_float4(o[i][0] * inv, o[i][1] * inv,
                                o[i][2] * inv, o[i][3] * inv);
        *reinterpret_cast<float4*>(
            &outg[(size_t)(row0 + r0o + i) * DMODEL + hoff + c0o]) = ov;
    }
}

// ---------------------------------------------------------------------------
extern "C" void kernel_launch(void* const* d_in, const int* in_sizes, int n_in,
                              void* d_out, int out_size)
{
    const float* x  = (const float*)d_in[0];
    const float* Wq = (const float*)d_in[1];
    const float* Wk = (const float*)d_in[2];
    const float* Wv = (const float*)d_in[3];
    const float* Wo = (const float*)d_in[4];
    const float* bo = (const float*)d_in[5];
    float* out = (float*)d_out;

    float *q, *k, *v, *at;
    cudaGetSymbolAddress((void**)&q,  g_q);
    cudaGetSymbolAddress((void**)&k,  g_k);
    cudaGetSymbolAddress((void**)&v,  g_v);
    cudaGetSymbolAddress((void**)&at, g_at);

    cudaFuncSetAttribute(attn_kernel,
                         cudaFuncAttributeMaxDynamicSharedMemorySize,
                         ATTN_SMEM_BYTES);

    // Fused QKV projections: one launch, z selects the weight/output pair.
    dim3 g1(DMODEL / 64, SEQ / 64, 3);
    gemm64<<<g1, 256>>>(x, Wq, Wk, Wv, nullptr, q, k, v, SEQ, DMODEL, DMODEL);

    // Causal flash attention.
    dim3 g2(SEQ / 64, HEADS);
    attn_kernel<<<g2, 256, ATTN_SMEM_BYTES>>>(q, k, v, at);

    // Output projection + bias, straight into d_out.
    dim3 g3(DMODEL / 64, SEQ / 64, 1);
    gemm64<<<g3, 256>>>(at, Wo, Wo, Wo, bo, out, out, out, SEQ, DMODEL, DMODEL);
}

// round 3
// speedup vs baseline: 1.2277x; 1.2277x over previous
#include <cuda_runtime.h>
#include <cuda_bf16.h>
#include <mma.h>
#include <cstdint>

using namespace nvcuda;

#define SEQ    4096
#define DMODEL 1024
#define HEADS  16
#define DHEAD  64

// ---------------- scratch (no cudaMalloc allowed) ----------------
__device__ float g_q[SEQ * DMODEL];
__device__ float g_k[SEQ * DMODEL];
__device__ float g_v[SEQ * DMODEL];
__device__ float g_at[SEQ * DMODEL];

__device__ __nv_bfloat16 g_xh[SEQ * DMODEL];
__device__ __nv_bfloat16 g_xl[SEQ * DMODEL];
__device__ __nv_bfloat16 g_ath[SEQ * DMODEL];
__device__ __nv_bfloat16 g_atl[SEQ * DMODEL];
// transposed weights [N][K], hi/lo
__device__ __nv_bfloat16 g_wqh[DMODEL * DMODEL];
__device__ __nv_bfloat16 g_wql[DMODEL * DMODEL];
__device__ __nv_bfloat16 g_wkh[DMODEL * DMODEL];
__device__ __nv_bfloat16 g_wkl[DMODEL * DMODEL];
__device__ __nv_bfloat16 g_wvh[DMODEL * DMODEL];
__device__ __nv_bfloat16 g_wvl[DMODEL * DMODEL];
__device__ __nv_bfloat16 g_woh[DMODEL * DMODEL];
__device__ __nv_bfloat16 g_wol[DMODEL * DMODEL];

__device__ __forceinline__ unsigned pk2(float a, float b) {
    __nv_bfloat162 t = __floats2bfloat162_rn(a, b);
    return *reinterpret_cast<unsigned*>(&t);
}

// ---------------- prep: elementwise hi/lo split (fp32 -> 2x bf16) ----------------
__global__ void __launch_bounds__(256) split_kernel(
    const float* __restrict__ src, __nv_bfloat16* __restrict__ hi,
    __nv_bfloat16* __restrict__ lo)
{
    int i = blockIdx.x * 256 + threadIdx.x;  // one float4 per thread
    float4 v = reinterpret_cast<const float4*>(src)[i];
    __nv_bfloat16 h0 = __float2bfloat16_rn(v.x);
    __nv_bfloat16 h1 = __float2bfloat16_rn(v.y);
    __nv_bfloat16 h2 = __float2bfloat16_rn(v.z);
    __nv_bfloat16 h3 = __float2bfloat16_rn(v.w);
    float r0 = v.x - __bfloat162float(h0);
    float r1 = v.y - __bfloat162float(h1);
    float r2 = v.z - __bfloat162float(h2);
    float r3 = v.w - __bfloat162float(h3);
    uint2 hv, lv;
    __nv_bfloat162 hh0 = {h0, h1}, hh1 = {h2, h3};
    hv.x = *reinterpret_cast<unsigned*>(&hh0);
    hv.y = *reinterpret_cast<unsigned*>(&hh1);
    lv.x = pk2(r0, r1);
    lv.y = pk2(r2, r3);
    reinterpret_cast<uint2*>(hi)[i] = hv;
    reinterpret_cast<uint2*>(lo)[i] = lv;
}

// ---------------- prep: weight transpose + hi/lo split ----------------
// W [K=1024][N=1024] row-major -> T_hi/T_lo [N][K] bf16. z selects matrix.
__global__ void __launch_bounds__(256) wsplit_kernel(
    const float* __restrict__ W0, const float* __restrict__ W1,
    const float* __restrict__ W2, const float* __restrict__ W3,
    __nv_bfloat16* H0, __nv_bfloat16* L0, __nv_bfloat16* H1, __nv_bfloat16* L1,
    __nv_bfloat16* H2, __nv_bfloat16* L2, __nv_bfloat16* H3, __nv_bfloat16* L3)
{
    const int z = blockIdx.z;
    const float* W = (z == 0) ? W0 : (z == 1) ? W1 : (z == 2) ? W2 : W3;
    __nv_bfloat16* H = (z == 0) ? H0 : (z == 1) ? H1 : (z == 2) ? H2 : H3;
    __nv_bfloat16* L = (z == 0) ? L0 : (z == 1) ? L1 : (z == 2) ? L2 : L3;

    __shared__ float ts[32][33];
    const int n0 = blockIdx.x * 32, k0 = blockIdx.y * 32;
    const int tx = threadIdx.x, ty = threadIdx.y;  // 32 x 8
#pragma unroll
    for (int r = 0; r < 4; r++)
        ts[ty + 8 * r][tx] = W[(size_t)(k0 + ty + 8 * r) * DMODEL + n0 + tx];
    __syncthreads();
#pragma unroll
    for (int r = 0; r < 4; r++) {
        int n = n0 + ty + 8 * r;
        float a = ts[tx][ty + 8 * r];
        __nv_bfloat16 h = __float2bfloat16_rn(a);
        H[(size_t)n * DMODEL + k0 + tx] = h;
        L[(size_t)n * DMODEL + k0 + tx] = __float2bfloat16_rn(a - __bfloat162float(h));
    }
}

// ---------------- WMMA split-bf16 GEMM ----------------
// C[4096,1024] = (Ah+Al)[M][K] x (Bh+Bl)^T, B stored [N][K] (so col_major frag).
// CTA tile 128x128, BK=32, 8 warps 4x2, warp tile 32x64. 3 passes hh+hl+lh.
#define LDM 40  // bf16 elems per smem row (80B) -> conflict-free ldmatrix

__global__ void __launch_bounds__(256) gemm_wmma(
    const __nv_bfloat16* __restrict__ Ah, const __nv_bfloat16* __restrict__ Al,
    const __nv_bfloat16* __restrict__ Bh0, const __nv_bfloat16* __restrict__ Bl0,
    const __nv_bfloat16* __restrict__ Bh1, const __nv_bfloat16* __restrict__ Bl1,
    const __nv_bfloat16* __restrict__ Bh2, const __nv_bfloat16* __restrict__ Bl2,
    float* C0, float* C1, float* C2)
{
    const int z = blockIdx.z;
    const __nv_bfloat16* Bh = (z == 0) ? Bh0 : (z == 1) ? Bh1 : Bh2;
    const __nv_bfloat16* Bl = (z == 0) ? Bl0 : (z == 1) ? Bl1 : Bl2;
    float* C = (z == 0) ? C0 : (z == 1) ? C1 : C2;

    __shared__ __nv_bfloat16 As[2][128 * LDM];
    __shared__ __nv_bfloat16 Bs[2][128 * LDM];

    const int tid = threadIdx.x;
    const int wid = tid >> 5;
    const int wm = wid & 3;       // 4 row groups of 32
    const int wn = wid >> 2;      // 2 col groups of 64
    const int m0 = blockIdx.y * 128;
    const int n0 = blockIdx.x * 128;

    wmma::fragment<wmma::accumulator, 16, 16, 16, float> acc[2][4];
#pragma unroll
    for (int i = 0; i < 2; i++)
#pragma unroll
        for (int j = 0; j < 4; j++) wmma::fill_fragment(acc[i][j], 0.0f);

    const int r  = tid >> 2;      // 0..63
    const int ch = tid & 3;       // 16B chunk within 32-elem row slab

    for (int kc = 0; kc < DMODEL; kc += 32) {
        // stage A/B hi+lo tiles (128 rows x 32 bf16, padded rows of LDM)
#pragma unroll
        for (int hf = 0; hf < 2; hf++) {
            const int row = r + hf * 64;
            const size_t go = (size_t)row * DMODEL + kc + ch * 8;
            const int so = row * LDM + ch * 8;
            *reinterpret_cast<uint4*>(&As[0][so]) =
                *reinterpret_cast<const uint4*>(&Ah[(size_t)m0 * DMODEL + go]);
            *reinterpret_cast<uint4*>(&As[1][so]) =
                *reinterpret_cast<const uint4*>(&Al[(size_t)m0 * DMODEL + go]);
            *reinterpret_cast<uint4*>(&Bs[0][so]) =
                *reinterpret_cast<const uint4*>(&Bh[(size_t)n0 * DMODEL + go]);
            *reinterpret_cast<uint4*>(&Bs[1][so]) =
                *reinterpret_cast<const uint4*>(&Bl[(size_t)n0 * DMODEL + go]);
        }
        __syncthreads();

#pragma unroll
        for (int ks = 0; ks < 32; ks += 16) {
            wmma::fragment<wmma::matrix_a, 16, 16, 16, __nv_bfloat16,
                           wmma::row_major> ah[2], al[2];
#pragma unroll
            for (int i = 0; i < 2; i++) {
                wmma::load_matrix_sync(ah[i], &As[0][(wm * 32 + 16 * i) * LDM + ks], LDM);
                wmma::load_matrix_sync(al[i], &As[1][(wm * 32 + 16 * i) * LDM + ks], LDM);
            }
#pragma unroll
            for (int j = 0; j < 4; j++) {
                wmma::fragment<wmma::matrix_b, 16, 16, 16, __nv_bfloat16,
                               wmma::col_major> bh, bl;
                wmma::load_matrix_sync(bh, &Bs[0][(wn * 64 + 16 * j) * LDM + ks], LDM);
                wmma::load_matrix_sync(bl, &Bs[1][(wn * 64 + 16 * j) * LDM + ks], LDM);
#pragma unroll
                for (int i = 0; i < 2; i++) {
                    wmma::mma_sync(acc[i][j], ah[i], bh, acc[i][j]);
                    wmma::mma_sync(acc[i][j], ah[i], bl, acc[i][j]);
                    wmma::mma_sync(acc[i][j], al[i], bh, acc[i][j]);
                }
            }
        }
        __syncthreads();
    }

#pragma unroll
    for (int i = 0; i < 2; i++)
#pragma unroll
        for (int j = 0; j < 4; j++)
            wmma::store_matrix_sync(
                &C[(size_t)(m0 + wm * 32 + 16 * i) * DMODEL + n0 + wn * 64 + 16 * j],
                acc[i][j], DMODEL, wmma::mem_row_major);
}

// ---------------- bias add epilogue ----------------
__global__ void __launch_bounds__(256) bias_add(
    float* __restrict__ out, const float* __restrict__ bo)
{
    int i = blockIdx.x * 256 + threadIdx.x;        // one float4
    float4 v = reinterpret_cast<float4*>(out)[i];
    float4 b = *reinterpret_cast<const float4*>(&bo[(i * 4) & (DMODEL - 1)]);
    v.x += b.x; v.y += b.y; v.z += b.z; v.w += b.w;
    reinterpret_cast<float4*>(out)[i] = v;
}

// ---------------- flash attention (fp32, proven in R1) ----------------
#define ATTN_SMEM_FLOATS (4096 * 3 + 64 * 68 + 192)
#define ATTN_SMEM_BYTES  (ATTN_SMEM_FLOATS * 4)

__global__ void __launch_bounds__(256) attn_kernel(
    const float* __restrict__ qg, const float* __restrict__ kg,
    const float* __restrict__ vg, float* __restrict__ outg)
{
    extern __shared__ float sm[];
    float* Qt   = sm;
    float* Ks   = sm + 4096;
    float* Vs   = sm + 8192;
    float* Ss   = sm + 12288;
    float* m_s  = sm + 12288 + 4352;
    float* l_s  = m_s + 64;
    float* sc_s = l_s + 64;

    const int tid  = threadIdx.x;
    const int h    = blockIdx.y;
    const int ib   = (int)(gridDim.x - 1u - blockIdx.x);
    const int row0 = ib * 64;
    const int hoff = h * DHEAD;
    const float beta = 0.125f;

    const int tx = tid & 15, ty = tid >> 4;
    const int kq0 = ty * 4;
    const int rq0 = tx * 4;
    const int r0o = ty * 4;
    const int c0o = tx * 4;

    {
        const int rr = tid >> 2;
        const int dbase = (tid & 3) * 16;
        const float* qp = qg + (size_t)(row0 + rr) * DMODEL + hoff + dbase;
#pragma unroll
        for (int u = 0; u < 4; u++) {
            float4 qv = *reinterpret_cast<const float4*>(qp + 4 * u);
            Qt[(dbase + 4 * u + 0) * 64 + rr] = qv.x * beta;
            Qt[(dbase + 4 * u + 1) * 64 + rr] = qv.y * beta;
            Qt[(dbase + 4 * u + 2) * 64 + rr] = qv.z * beta;
            Qt[(dbase + 4 * u + 3) * 64 + rr] = qv.w * beta;
        }
    }
    if (tid < 64) { m_s[tid] = -1e30f; l_s[tid] = 0.f; }

    float o[4][4] = {};

    for (int jb = 0; jb <= ib; jb++) {
        __syncthreads();
        {
            const int kv = tid >> 2;
            const int dbase = (tid & 3) * 16;
            const float* kp = kg + (size_t)(jb * 64 + kv) * DMODEL + hoff + dbase;
            const float* vp = vg + (size_t)(jb * 64 + kv) * DMODEL + hoff + dbase;
#pragma unroll
            for (int u = 0; u < 4; u++) {
                *reinterpret_cast<float4*>(&Ks[kv * 64 + dbase + 4 * u]) =
                    *reinterpret_cast<const float4*>(kp + 4 * u);
                *reinterpret_cast<float4*>(&Vs[kv * 64 + dbase + 4 * u]) =
                    *reinterpret_cast<const float4*>(vp + 4 * u);
            }
        }
        __syncthreads();

        float s[4][4] = {};
#pragma unroll 16
        for (int kk = 0; kk < 64; kk++) {
            float a0 = Ks[(kq0 + 0) * 64 + kk];
            float a1 = Ks[(kq0 + 1) * 64 + kk];
            float a2 = Ks[(kq0 + 2) * 64 + kk];
            float a3 = Ks[(kq0 + 3) * 64 + kk];
            float4 b = *reinterpret_cast<const float4*>(&Qt[kk * 64 + rq0]);
            s[0][0] += a0 * b.x; s[0][1] += a0 * b.y; s[0][2] += a0 * b.z; s[0][3] += a0 * b.w;
            s[1][0] += a1 * b.x; s[1][1] += a1 * b.y; s[1][2] += a1 * b.z; s[1][3] += a1 * b.w;
            s[2][0] += a2 * b.x; s[2][1] += a2 * b.y; s[2][2] += a2 * b.z; s[2][3] += a2 * b.w;
            s[3][0] += a3 * b.x; s[3][1] += a3 * b.y; s[3][2] += a3 * b.z; s[3][3] += a3 * b.w;
        }
        if (jb == ib) {
#pragma unroll
            for (int i = 0; i < 4; i++)
#pragma unroll
                for (int j = 0; j < 4; j++)
                    if (kq0 + i > rq0 + j) s[i][j] = -1e30f;
        }
#pragma unroll
        for (int i = 0; i < 4; i++)
            *reinterpret_cast<float4*>(&Ss[(kq0 + i) * 68 + rq0]) =
                make_float4(s[i][0], s[i][1], s[i][2], s[i][3]);
        __syncthreads();

        {
            const int row = tid >> 2, sub = tid & 3;
            float mx = -1e30f;
#pragma unroll
            for (int t = 0; t < 16; t++) {
                int kk = t * 4 + sub;
                mx = fmaxf(mx, Ss[kk * 68 + row]);
            }
            mx = fmaxf(mx, __shfl_xor_sync(0xffffffffu, mx, 1));
            mx = fmaxf(mx, __shfl_xor_sync(0xffffffffu, mx, 2));
            float mold = m_s[row];
            float mnew = fmaxf(mold, mx);
            float sum = 0.f;
#pragma unroll
            for (int t = 0; t < 16; t++) {
                int kk = t * 4 + sub;
                float p = __expf(Ss[kk * 68 + row] - mnew);
                Ss[kk * 68 + row] = p;
                sum += p;
            }
            sum += __shfl_xor_sync(0xffffffffu, sum, 1);
            sum += __shfl_xor_sync(0xffffffffu, sum, 2);
            if (sub == 0) {
                float sc = __expf(mold - mnew);
                sc_s[row] = sc;
                l_s[row] = l_s[row] * sc + sum;
                m_s[row] = mnew;
            }
        }
        __syncthreads();

        {
            float s0 = sc_s[r0o + 0], s1 = sc_s[r0o + 1],
                  s2 = sc_s[r0o + 2], s3 = sc_s[r0o + 3];
#pragma unroll
            for (int j = 0; j < 4; j++) {
                o[0][j] *= s0; o[1][j] *= s1; o[2][j] *= s2; o[3][j] *= s3;
            }
        }
#pragma unroll 16
        for (int kk = 0; kk < 64; kk++) {
            float4 a = *reinterpret_cast<const float4*>(&Ss[kk * 68 + r0o]);
            float4 b = *reinterpret_cast<const float4*>(&Vs[kk * 64 + c0o]);
            o[0][0] += a.x * b.x; o[0][1] += a.x * b.y; o[0][2] += a.x * b.z; o[0][3] += a.x * b.w;
            o[1][0] += a.y * b.x; o[1][1] += a.y * b.y; o[1][2] += a.y * b.z; o[1][3] += a.y * b.w;
            o[2][0] += a.z * b.x; o[2][1] += a.z * b.y; o[2][2] += a.z * b.z; o[2][3] += a.z * b.w;
            o[3][0] += a.w * b.x; o[3][1] += a.w * b.y; o[3][2] += a.w * b.z; o[3][3] += a.w * b.w;
        }
    }

    __syncthreads();
#pragma unroll
    for (int i = 0; i < 4; i++) {
        float inv = 1.0f / l_s[r0o + i];
        float4 ov = make_float4(o[i][0] * inv, o[i][1] * inv,
                                o[i][2] * inv, o[i][3] * inv);
        *reinterpret_cast<float4*>(
            &outg[(size_t)(row0 + r0o + i) * DMODEL + hoff + c0o]) = ov;
    }
}

// ---------------------------------------------------------------------------
extern "C" void kernel_launch(void* const* d_in, const int* in_sizes, int n_in,
                              void* d_out, int out_size)
{
    const float* x  = (const float*)d_in[0];
    const float* Wq = (const float*)d_in[1];
    const float* Wk = (const float*)d_in[2];
    const float* Wv = (const float*)d_in[3];
    const float* Wo = (const float*)d_in[4];
    const float* bo = (const float*)d_in[5];
    float* out = (float*)d_out;

    float *q, *k, *v, *at;
    __nv_bfloat16 *xh, *xl, *ath, *atl;
    __nv_bfloat16 *wqh, *wql, *wkh, *wkl, *wvh, *wvl, *woh, *wol;
    cudaGetSymbolAddress((void**)&q,  g_q);
    cudaGetSymbolAddress((void**)&k,  g_k);
    cudaGetSymbolAddress((void**)&v,  g_v);
    cudaGetSymbolAddress((void**)&at, g_at);
    cudaGetSymbolAddress((void**)&xh,  g_xh);
    cudaGetSymbolAddress((void**)&xl,  g_xl);
    cudaGetSymbolAddress((void**)&ath, g_ath);
    cudaGetSymbolAddress((void**)&atl, g_atl);
    cudaGetSymbolAddress((void**)&wqh, g_wqh);
    cudaGetSymbolAddress((void**)&wql, g_wql);
    cudaGetSymbolAddress((void**)&wkh, g_wkh);
    cudaGetSymbolAddress((void**)&wkl, g_wkl);
    cudaGetSymbolAddress((void**)&wvh, g_wvh);
    cudaGetSymbolAddress((void**)&wvl, g_wvl);
    cudaGetSymbolAddress((void**)&woh, g_woh);
    cudaGetSymbolAddress((void**)&wol, g_wol);

    cudaFuncSetAttribute(attn_kernel,
                         cudaFuncAttributeMaxDynamicSharedMemorySize,
                         ATTN_SMEM_BYTES);

    // prep: split x, transpose+split all weights
    split_kernel<<<SEQ * DMODEL / 1024, 256>>>(x, xh, xl);
    dim3 gw(DMODEL / 32, DMODEL / 32, 4);
    wsplit_kernel<<<gw, dim3(32, 8)>>>(Wq, Wk, Wv, Wo,
        wqh, wql, wkh, wkl, wvh, wvl, woh, wol);

    // QKV projections on tensor cores (WMMA/HMMA)
    dim3 g1(DMODEL / 128, SEQ / 128, 3);
    gemm_wmma<<<g1, 256>>>(xh, xl,
        wqh, wql, wkh, wkl, wvh, wvl, q, k, v);

    // causal flash attention (fp32)
    dim3 g2(SEQ / 64, HEADS);
    attn_kernel<<<g2, 256, ATTN_SMEM_BYTES>>>(q, k, v, at);

    // split attention output, then Wo projection
    split_kernel<<<SEQ * DMODEL / 1024, 256>>>(at, ath, atl);
    dim3 g3(DMODEL / 128, SEQ / 128, 1);
    gemm_wmma<<<g3, 256>>>(ath, atl,
        woh, wol, woh, wol, woh, wol, out, out, out);

    // bias epilogue
    bias_add<<<SEQ * DMODEL / 1024, 256>>>(out, bo);
}

// round 5
// speedup vs baseline: 1.6726x; 1.3623x over previous
#include <cuda_runtime.h>
#include <cuda_bf16.h>
#include <mma.h>
#include <cstdint>

using namespace nvcuda;

#define SEQ    4096
#define DMODEL 1024
#define HEADS  16
#define DHEAD  64

// ---------------- scratch (no cudaMalloc allowed) ----------------
__device__ float g_q[SEQ * DMODEL];
__device__ float g_k[SEQ * DMODEL];
__device__ float g_v[SEQ * DMODEL];
__device__ float g_at[SEQ * DMODEL];

__device__ __nv_bfloat16 g_xh[SEQ * DMODEL];
__device__ __nv_bfloat16 g_xl[SEQ * DMODEL];
__device__ __nv_bfloat16 g_ath[SEQ * DMODEL];
__device__ __nv_bfloat16 g_atl[SEQ * DMODEL];
// transposed weights [N][K], hi/lo
__device__ __nv_bfloat16 g_wqh[DMODEL * DMODEL];
__device__ __nv_bfloat16 g_wql[DMODEL * DMODEL];
__device__ __nv_bfloat16 g_wkh[DMODEL * DMODEL];
__device__ __nv_bfloat16 g_wkl[DMODEL * DMODEL];
__device__ __nv_bfloat16 g_wvh[DMODEL * DMODEL];
__device__ __nv_bfloat16 g_wvl[DMODEL * DMODEL];
__device__ __nv_bfloat16 g_woh[DMODEL * DMODEL];
__device__ __nv_bfloat16 g_wol[DMODEL * DMODEL];

__device__ __forceinline__ unsigned pk2(float a, float b) {
    __nv_bfloat162 t = __floats2bfloat162_rn(a, b);
    return *reinterpret_cast<unsigned*>(&t);
}

// ---------------- prep: elementwise hi/lo split (fp32 -> 2x bf16) ----------------
__global__ void __launch_bounds__(256) split_kernel(
    const float* __restrict__ src, __nv_bfloat16* __restrict__ hi,
    __nv_bfloat16* __restrict__ lo)
{
    int i = blockIdx.x * 256 + threadIdx.x;
    float4 v = reinterpret_cast<const float4*>(src)[i];
    __nv_bfloat16 h0 = __float2bfloat16_rn(v.x);
    __nv_bfloat16 h1 = __float2bfloat16_rn(v.y);
    __nv_bfloat16 h2 = __float2bfloat16_rn(v.z);
    __nv_bfloat16 h3 = __float2bfloat16_rn(v.w);
    float r0 = v.x - __bfloat162float(h0);
    float r1 = v.y - __bfloat162float(h1);
    float r2 = v.z - __bfloat162float(h2);
    float r3 = v.w - __bfloat162float(h3);
    uint2 hv, lv;
    __nv_bfloat162 hh0 = {h0, h1}, hh1 = {h2, h3};
    hv.x = *reinterpret_cast<unsigned*>(&hh0);
    hv.y = *reinterpret_cast<unsigned*>(&hh1);
    lv.x = pk2(r0, r1);
    lv.y = pk2(r2, r3);
    reinterpret_cast<uint2*>(hi)[i] = hv;
    reinterpret_cast<uint2*>(lo)[i] = lv;
}

// ---------------- prep: weight transpose + hi/lo split ----------------
__global__ void __launch_bounds__(256) wsplit_kernel(
    const float* __restrict__ W0, const float* __restrict__ W1,
    const float* __restrict__ W2, const float* __restrict__ W3,
    __nv_bfloat16* H0, __nv_bfloat16* L0, __nv_bfloat16* H1, __nv_bfloat16* L1,
    __nv_bfloat16* H2, __nv_bfloat16* L2, __nv_bfloat16* H3, __nv_bfloat16* L3)
{
    const int z = blockIdx.z;
    const float* W = (z == 0) ? W0 : (z == 1) ? W1 : (z == 2) ? W2 : W3;
    __nv_bfloat16* H = (z == 0) ? H0 : (z == 1) ? H1 : (z == 2) ? H2 : H3;
    __nv_bfloat16* L = (z == 0) ? L0 : (z == 1) ? L1 : (z == 2) ? L2 : L3;

    __shared__ float ts[32][33];
    const int n0 = blockIdx.x * 32, k0 = blockIdx.y * 32;
    const int tx = threadIdx.x, ty = threadIdx.y;  // 32 x 8
#pragma unroll
    for (int r = 0; r < 4; r++)
        ts[ty + 8 * r][tx] = W[(size_t)(k0 + ty + 8 * r) * DMODEL + n0 + tx];
    __syncthreads();
#pragma unroll
    for (int r = 0; r < 4; r++) {
        int n = n0 + ty + 8 * r;
        float a = ts[tx][ty + 8 * r];
        __nv_bfloat16 h = __float2bfloat16_rn(a);
        H[(size_t)n * DMODEL + k0 + tx] = h;
        L[(size_t)n * DMODEL + k0 + tx] = __float2bfloat16_rn(a - __bfloat162float(h));
    }
}

// ---------------- WMMA split-bf16 GEMM (unchanged from R3) ----------------
#define LDM 40

__global__ void __launch_bounds__(256) gemm_wmma(
    const __nv_bfloat16* __restrict__ Ah, const __nv_bfloat16* __restrict__ Al,
    const __nv_bfloat16* __restrict__ Bh0, const __nv_bfloat16* __restrict__ Bl0,
    const __nv_bfloat16* __restrict__ Bh1, const __nv_bfloat16* __restrict__ Bl1,
    const __nv_bfloat16* __restrict__ Bh2, const __nv_bfloat16* __restrict__ Bl2,
    float* C0, float* C1, float* C2)
{
    const int z = blockIdx.z;
    const __nv_bfloat16* Bh = (z == 0) ? Bh0 : (z == 1) ? Bh1 : Bh2;
    const __nv_bfloat16* Bl = (z == 0) ? Bl0 : (z == 1) ? Bl1 : Bl2;
    float* C = (z == 0) ? C0 : (z == 1) ? C1 : C2;

    __shared__ __nv_bfloat16 As[2][128 * LDM];
    __shared__ __nv_bfloat16 Bs[2][128 * LDM];

    const int tid = threadIdx.x;
    const int wid = tid >> 5;
    const int wm = wid & 3;
    const int wn = wid >> 2;
    const int m0 = blockIdx.y * 128;
    const int n0 = blockIdx.x * 128;

    wmma::fragment<wmma::accumulator, 16, 16, 16, float> acc[2][4];
#pragma unroll
    for (int i = 0; i < 2; i++)
#pragma unroll
        for (int j = 0; j < 4; j++) wmma::fill_fragment(acc[i][j], 0.0f);

    const int r  = tid >> 2;
    const int ch = tid & 3;

    for (int kc = 0; kc < DMODEL; kc += 32) {
#pragma unroll
        for (int hf = 0; hf < 2; hf++) {
            const int row = r + hf * 64;
            const size_t go = (size_t)row * DMODEL + kc + ch * 8;
            const int so = row * LDM + ch * 8;
            *reinterpret_cast<uint4*>(&As[0][so]) =
                *reinterpret_cast<const uint4*>(&Ah[(size_t)m0 * DMODEL + go]);
            *reinterpret_cast<uint4*>(&As[1][so]) =
                *reinterpret_cast<const uint4*>(&Al[(size_t)m0 * DMODEL + go]);
            *reinterpret_cast<uint4*>(&Bs[0][so]) =
                *reinterpret_cast<const uint4*>(&Bh[(size_t)n0 * DMODEL + go]);
            *reinterpret_cast<uint4*>(&Bs[1][so]) =
                *reinterpret_cast<const uint4*>(&Bl[(size_t)n0 * DMODEL + go]);
        }
        __syncthreads();

#pragma unroll
        for (int ks = 0; ks < 32; ks += 16) {
            wmma::fragment<wmma::matrix_a, 16, 16, 16, __nv_bfloat16,
                           wmma::row_major> ah[2], al[2];
#pragma unroll
            for (int i = 0; i < 2; i++) {
                wmma::load_matrix_sync(ah[i], &As[0][(wm * 32 + 16 * i) * LDM + ks], LDM);
                wmma::load_matrix_sync(al[i], &As[1][(wm * 32 + 16 * i) * LDM + ks], LDM);
            }
#pragma unroll
            for (int j = 0; j < 4; j++) {
                wmma::fragment<wmma::matrix_b, 16, 16, 16, __nv_bfloat16,
                               wmma::col_major> bh, bl;
                wmma::load_matrix_sync(bh, &Bs[0][(wn * 64 + 16 * j) * LDM + ks], LDM);
                wmma::load_matrix_sync(bl, &Bs[1][(wn * 64 + 16 * j) * LDM + ks], LDM);
#pragma unroll
                for (int i = 0; i < 2; i++) {
                    wmma::mma_sync(acc[i][j], ah[i], bh, acc[i][j]);
                    wmma::mma_sync(acc[i][j], ah[i], bl, acc[i][j]);
                    wmma::mma_sync(acc[i][j], al[i], bh, acc[i][j]);
                }
            }
        }
        __syncthreads();
    }

#pragma unroll
    for (int i = 0; i < 2; i++)
#pragma unroll
        for (int j = 0; j < 4; j++)
            wmma::store_matrix_sync(
                &C[(size_t)(m0 + wm * 32 + 16 * i) * DMODEL + n0 + wn * 64 + 16 * j],
                acc[i][j], DMODEL, wmma::mem_row_major);
}

// ---------------- bias add epilogue ----------------
__global__ void __launch_bounds__(256) bias_add(
    float* __restrict__ out, const float* __restrict__ bo)
{
    int i = blockIdx.x * 256 + threadIdx.x;
    float4 v = reinterpret_cast<float4*>(out)[i];
    float4 b = *reinterpret_cast<const float4*>(&bo[(i * 4) & (DMODEL - 1)]);
    v.x += b.x; v.y += b.y; v.z += b.z; v.w += b.w;
    reinterpret_cast<float4*>(out)[i] = v;
}

// ---------------- WMMA flash attention (split-bf16 both matmuls) ----------------
// CTA = (64-row query block, head). 8 warps. Per 64-key tile:
//   S = Q·K^T (3-pass split-bf16 WMMA) -> fp32 smem -> online softmax ->
//   P hi/lo bf16 -> O_part = P·V (3-pass WMMA) -> staged via smem ->
//   per-thread fp32 accumulators with running rescale.
#define LP 72                       // bf16 tile pitch (elems)
#define LSP 68                      // fp32 S pitch
#define AOFF_QH 0
#define AOFF_QL 9216
#define AOFF_KH 18432
#define AOFF_KL 27648
#define AOFF_VH 36864
#define AOFF_VL 46080
#define AOFF_S  55296               // fp32 64*68*4 = 17408
#define AOFF_M  72704
#define AOFF_L  72960
#define AOFF_SC 73216
#define AOFF_PH 73472
#define AOFF_PL 82688
#define ATTN2_BYTES 91904

__device__ __forceinline__ void cvt_store4(char* base, int off, int idx,
                                           float4 v, float scale)
{
    __nv_bfloat16* H = reinterpret_cast<__nv_bfloat16*>(base + off);
    __nv_bfloat16* L = reinterpret_cast<__nv_bfloat16*>(base + off + (AOFF_QL - AOFF_QH));
    float a0 = v.x * scale, a1 = v.y * scale, a2 = v.z * scale, a3 = v.w * scale;
    __nv_bfloat16 h0 = __float2bfloat16_rn(a0);
    __nv_bfloat16 h1 = __float2bfloat16_rn(a1);
    __nv_bfloat16 h2 = __float2bfloat16_rn(a2);
    __nv_bfloat16 h3 = __float2bfloat16_rn(a3);
    uint2 hw, lw;
    __nv_bfloat162 p0 = {h0, h1}, p1 = {h2, h3};
    hw.x = *reinterpret_cast<unsigned*>(&p0);
    hw.y = *reinterpret_cast<unsigned*>(&p1);
    lw.x = pk2(a0 - __bfloat162float(h0), a1 - __bfloat162float(h1));
    lw.y = pk2(a2 - __bfloat162float(h2), a3 - __bfloat162float(h3));
    *reinterpret_cast<uint2*>(H + idx) = hw;
    *reinterpret_cast<uint2*>(L + idx) = lw;
}

__global__ void __launch_bounds__(256) attn_wmma(
    const float* __restrict__ qg, const float* __restrict__ kg,
    const float* __restrict__ vg, float* __restrict__ outg)
{
    extern __shared__ char smc[];
    __nv_bfloat16* Qh = reinterpret_cast<__nv_bfloat16*>(smc + AOFF_QH);
    __nv_bfloat16* Ql = reinterpret_cast<__nv_bfloat16*>(smc + AOFF_QL);
    __nv_bfloat16* Kh = reinterpret_cast<__nv_bfloat16*>(smc + AOFF_KH);
    __nv_bfloat16* Vh = reinterpret_cast<__nv_bfloat16*>(smc + AOFF_VH);
    __nv_bfloat16* Ph = reinterpret_cast<__nv_bfloat16*>(smc + AOFF_PH);
    __nv_bfloat16* Pl = reinterpret_cast<__nv_bfloat16*>(smc + AOFF_PL);
    float* S    = reinterpret_cast<float*>(smc + AOFF_S);
    float* m_s  = reinterpret_cast<float*>(smc + AOFF_M);
    float* l_s  = reinterpret_cast<float*>(smc + AOFF_L);
    float* sc_s = reinterpret_cast<float*>(smc + AOFF_SC);

    const int tid  = threadIdx.x;
    const int warp = tid >> 5;
    const int h    = blockIdx.y;
    const int ib   = (int)(gridDim.x - 1u - blockIdx.x);  // heavy first
    const int row0 = ib * 64;
    const int hoff = h * DHEAD;

    const int tm  = warp & 3;        // warp row tile (16 rows)
    const int tnb = (warp >> 2) * 2; // warp col tile base (2 tiles of 16)

    const int row = tid >> 2;        // 0..63 (loader/softmax row)
    const int cb  = (tid & 3) * 16;  // 16-col slab
    const int sub = tid & 3;

    // -------- load Q (pre-scaled by beta), split hi/lo --------
    {
        const float* qp = qg + (size_t)(row0 + row) * DMODEL + hoff + cb;
#pragma unroll
        for (int u = 0; u < 4; u++) {
            float4 v = *reinterpret_cast<const float4*>(qp + 4 * u);
            cvt_store4(smc, AOFF_QH, row * LP + cb + 4 * u, v, 0.125f);
        }
    }
    if (tid < 64) { m_s[tid] = -1e30f; l_s[tid] = 0.f; }

    float oacc[16];
#pragma unroll
    for (int t = 0; t < 16; t++) oacc[t] = 0.f;

    for (int jb = 0; jb <= ib; jb++) {
        // -------- load K, V tiles, split hi/lo --------
        {
            const float* kp = kg + (size_t)(jb * 64 + row) * DMODEL + hoff + cb;
            const float* vp = vg + (size_t)(jb * 64 + row) * DMODEL + hoff + cb;
#pragma unroll
            for (int u = 0; u < 4; u++) {
                float4 kv4 = *reinterpret_cast<const float4*>(kp + 4 * u);
                float4 vv4 = *reinterpret_cast<const float4*>(vp + 4 * u);
                cvt_store4(smc, AOFF_KH, row * LP + cb + 4 * u, kv4, 1.0f);
                cvt_store4(smc, AOFF_VH, row * LP + cb + 4 * u, vv4, 1.0f);
            }
        }
        __syncthreads();

        // -------- S = Q · K^T (3-pass split) --------
        {
            wmma::fragment<wmma::accumulator, 16, 16, 16, float> sacc[2];
            wmma::fill_fragment(sacc[0], 0.0f);
            wmma::fill_fragment(sacc[1], 0.0f);
#pragma unroll
            for (int kf = 0; kf < 4; kf++) {
                wmma::fragment<wmma::matrix_a, 16, 16, 16, __nv_bfloat16,
                               wmma::row_major> ah, al;
                wmma::load_matrix_sync(ah, &Qh[(tm * 16) * LP + kf * 16], LP);
                wmma::load_matrix_sync(al, &Ql[(tm * 16) * LP + kf * 16], LP);
#pragma unroll
                for (int t = 0; t < 2; t++) {
                    wmma::fragment<wmma::matrix_b, 16, 16, 16, __nv_bfloat16,
                                   wmma::col_major> bh, bl;
                    const int kr = (tnb + t) * 16;
                    wmma::load_matrix_sync(bh, &Kh[kr * LP + kf * 16], LP);
                    wmma::load_matrix_sync(bl, reinterpret_cast<__nv_bfloat16*>(
                        smc + AOFF_KL) + kr * LP + kf * 16, LP);
                    wmma::mma_sync(sacc[t], ah, bh, sacc[t]);
                    wmma::mma_sync(sacc[t], ah, bl, sacc[t]);
                    wmma::mma_sync(sacc[t], al, bh, sacc[t]);
                }
            }
#pragma unroll
            for (int t = 0; t < 2; t++)
                wmma::store_matrix_sync(&S[(tm * 16) * LSP + (tnb + t) * 16],
                                        sacc[t], LSP, wmma::mem_row_major);
        }
        __syncthreads();

        // -------- online softmax (4 lanes per row), P -> hi/lo bf16 --------
        {
            const bool diag = (jb == ib);
            float sv[16];
            float mx = -1e30f;
#pragma unroll
            for (int t = 0; t < 16; t++) {
                int c = sub + 4 * t;
                float s = S[row * LSP + c];
                if (diag && c > row) s = -1e30f;
                sv[t] = s;
                mx = fmaxf(mx, s);
            }
            mx = fmaxf(mx, __shfl_xor_sync(0xffffffffu, mx, 1));
            mx = fmaxf(mx, __shfl_xor_sync(0xffffffffu, mx, 2));
            float mold = m_s[row];
            float mnew = fmaxf(mold, mx);
            float sum = 0.f;
#pragma unroll
            for (int t = 0; t < 16; t++) {
                int c = sub + 4 * t;
                float p = __expf(sv[t] - mnew);
                sum += p;
                __nv_bfloat16 ph = __float2bfloat16_rn(p);
                Ph[row * LP + c] = ph;
                Pl[row * LP + c] = __float2bfloat16_rn(p - __bfloat162float(ph));
            }
            sum += __shfl_xor_sync(0xffffffffu, sum, 1);
            sum += __shfl_xor_sync(0xffffffffu, sum, 2);
            if (sub == 0) {
                float sc = __expf(mold - mnew);
                sc_s[row] = sc;
                l_s[row] = l_s[row] * sc + sum;
                m_s[row] = mnew;
            }
        }
        __syncthreads();

        // -------- O_part = P · V (3-pass split), staged via S smem --------
        {
            wmma::fragment<wmma::accumulator, 16, 16, 16, float> occ[2];
            wmma::fill_fragment(occ[0], 0.0f);
            wmma::fill_fragment(occ[1], 0.0f);
#pragma unroll
            for (int kf = 0; kf < 4; kf++) {
                wmma::fragment<wmma::matrix_a, 16, 16, 16, __nv_bfloat16,
                               wmma::row_major> ah, al;
                wmma::load_matrix_sync(ah, &Ph[(tm * 16) * LP + kf * 16], LP);
                wmma::load_matrix_sync(al, &Pl[(tm * 16) * LP + kf * 16], LP);
#pragma unroll
                for (int t = 0; t < 2; t++) {
                    wmma::fragment<wmma::matrix_b, 16, 16, 16, __nv_bfloat16,
                                   wmma::row_major> bh, bl;
                    const int nc = (tnb + t) * 16;
                    wmma::load_matrix_sync(bh, &Vh[(kf * 16) * LP + nc], LP);
                    wmma::load_matrix_sync(bl, reinterpret_cast<__nv_bfloat16*>(
                        smc + AOFF_VL) + (kf * 16) * LP + nc, LP);
                    wmma::mma_sync(occ[t], ah, bh, occ[t]);
                    wmma::mma_sync(occ[t], ah, bl, occ[t]);
                    wmma::mma_sync(occ[t], al, bh, occ[t]);
                }
            }
#pragma unroll
            for (int t = 0; t < 2; t++)
                wmma::store_matrix_sync(&S[(tm * 16) * LSP + (tnb + t) * 16],
                                        occ[t], LSP, wmma::mem_row_major);
        }
        __syncthreads();

        // -------- rescale + accumulate (reads S region + sc_s only) --------
        {
            float sc = sc_s[row];
#pragma unroll
            for (int t = 0; t < 16; t++)
                oacc[t] = oacc[t] * sc + S[row * LSP + sub + 4 * t];
        }
        __syncthreads();   // protect Ph/Kh/Vh before next iteration's writes
    }

    // -------- final normalize + write --------
    {
        float inv = 1.0f / l_s[row];
        float* dst = outg + (size_t)(row0 + row) * DMODEL + hoff;
#pragma unroll
        for (int t = 0; t < 16; t++)
            dst[sub + 4 * t] = oacc[t] * inv;
    }
}

// ---------------------------------------------------------------------------
extern "C" void kernel_launch(void* const* d_in, const int* in_sizes, int n_in,
                              void* d_out, int out_size)
{
    const float* x  = (const float*)d_in[0];
    const float* Wq = (const float*)d_in[1];
    const float* Wk = (const float*)d_in[2];
    const float* Wv = (const float*)d_in[3];
    const float* Wo = (const float*)d_in[4];
    const float* bo = (const float*)d_in[5];
    float* out = (float*)d_out;

    float *q, *k, *v, *at;
    __nv_bfloat16 *xh, *xl, *ath, *atl;
    __nv_bfloat16 *wqh, *wql, *wkh, *wkl, *wvh, *wvl, *woh, *wol;
    cudaGetSymbolAddress((void**)&q,  g_q);
    cudaGetSymbolAddress((void**)&k,  g_k);
    cudaGetSymbolAddress((void**)&v,  g_v);
    cudaGetSymbolAddress((void**)&at, g_at);
    cudaGetSymbolAddress((void**)&xh,  g_xh);
    cudaGetSymbolAddress((void**)&xl,  g_xl);
    cudaGetSymbolAddress((void**)&ath, g_ath);
    cudaGetSymbolAddress((void**)&atl, g_atl);
    cudaGetSymbolAddress((void**)&wqh, g_wqh);
    cudaGetSymbolAddress((void**)&wql, g_wql);
    cudaGetSymbolAddress((void**)&wkh, g_wkh);
    cudaGetSymbolAddress((void**)&wkl, g_wkl);
    cudaGetSymbolAddress((void**)&wvh, g_wvh);
    cudaGetSymbolAddress((void**)&wvl, g_wvl);
    cudaGetSymbolAddress((void**)&woh, g_woh);
    cudaGetSymbolAddress((void**)&wol, g_wol);

    cudaFuncSetAttribute(attn_wmma,
                         cudaFuncAttributeMaxDynamicSharedMemorySize,
                         ATTN2_BYTES);

    // prep: split x, transpose+split all weights
    split_kernel<<<SEQ * DMODEL / 1024, 256>>>(x, xh, xl);
    dim3 gw(DMODEL / 32, DMODEL / 32, 4);
    wsplit_kernel<<<gw, dim3(32, 8)>>>(Wq, Wk, Wv, Wo,
        wqh, wql, wkh, wkl, wvh, wvl, woh, wol);

    // QKV projections (tensor cores)
    dim3 g1(DMODEL / 128, SEQ / 128, 3);
    gemm_wmma<<<g1, 256>>>(xh, xl,
        wqh, wql, wkh, wkl, wvh, wvl, q, k, v);

    // causal flash attention (tensor cores)
    dim3 g2(SEQ / 64, HEADS);
    attn_wmma<<<g2, 256, ATTN2_BYTES>>>(q, k, v, at);

    // split attention output, then Wo projection
    split_kernel<<<SEQ * DMODEL / 1024, 256>>>(at, ath, atl);
    dim3 g3(DMODEL / 128, SEQ / 128, 1);
    gemm_wmma<<<g3, 256>>>(ath, atl,
        woh, wol, woh, wol, woh, wol, out, out, out);

    // bias epilogue
    bias_add<<<SEQ * DMODEL / 1024, 256>>>(out, bo);
}

// round 7
// speedup vs baseline: 2.2450x; 1.3423x over previous
#include <cuda_runtime.h>
#include <cuda_bf16.h>
#include <mma.h>
#include <cstdint>

using namespace nvcuda;

#define SEQ    4096
#define DMODEL 1024
#define HEADS  16
#define DHEAD  64

// ---------------- scratch (no cudaMalloc allowed) ----------------
__device__ float g_q[SEQ * DMODEL];
__device__ float g_k[SEQ * DMODEL];
__device__ float g_v[SEQ * DMODEL];
__device__ float g_at[SEQ * DMODEL];

__device__ __nv_bfloat16 g_xh[SEQ * DMODEL];
__device__ __nv_bfloat16 g_xl[SEQ * DMODEL];
__device__ __nv_bfloat16 g_ath[SEQ * DMODEL];
__device__ __nv_bfloat16 g_atl[SEQ * DMODEL];
__device__ __nv_bfloat16 g_wqh[DMODEL * DMODEL];
__device__ __nv_bfloat16 g_wql[DMODEL * DMODEL];
__device__ __nv_bfloat16 g_wkh[DMODEL * DMODEL];
__device__ __nv_bfloat16 g_wkl[DMODEL * DMODEL];
__device__ __nv_bfloat16 g_wvh[DMODEL * DMODEL];
__device__ __nv_bfloat16 g_wvl[DMODEL * DMODEL];
__device__ __nv_bfloat16 g_woh[DMODEL * DMODEL];
__device__ __nv_bfloat16 g_wol[DMODEL * DMODEL];

__device__ __forceinline__ unsigned pk2(float a, float b) {
    __nv_bfloat162 t = __floats2bfloat162_rn(a, b);
    return *reinterpret_cast<unsigned*>(&t);
}

__device__ __forceinline__ uint32_t smem_u32(const void* p) {
    uint32_t a;
    asm("{ .reg .u64 t; cvta.to.shared.u64 t, %1; cvt.u32.u64 %0, t; }"
        : "=r"(a) : "l"(p));
    return a;
}

// ---------------- prep kernels (unchanged) ----------------
__global__ void __launch_bounds__(256) split_kernel(
    const float* __restrict__ src, __nv_bfloat16* __restrict__ hi,
    __nv_bfloat16* __restrict__ lo)
{
    int i = blockIdx.x * 256 + threadIdx.x;
    float4 v = reinterpret_cast<const float4*>(src)[i];
    __nv_bfloat16 h0 = __float2bfloat16_rn(v.x);
    __nv_bfloat16 h1 = __float2bfloat16_rn(v.y);
    __nv_bfloat16 h2 = __float2bfloat16_rn(v.z);
    __nv_bfloat16 h3 = __float2bfloat16_rn(v.w);
    float r0 = v.x - __bfloat162float(h0);
    float r1 = v.y - __bfloat162float(h1);
    float r2 = v.z - __bfloat162float(h2);
    float r3 = v.w - __bfloat162float(h3);
    uint2 hv, lv;
    __nv_bfloat162 hh0 = {h0, h1}, hh1 = {h2, h3};
    hv.x = *reinterpret_cast<unsigned*>(&hh0);
    hv.y = *reinterpret_cast<unsigned*>(&hh1);
    lv.x = pk2(r0, r1);
    lv.y = pk2(r2, r3);
    reinterpret_cast<uint2*>(hi)[i] = hv;
    reinterpret_cast<uint2*>(lo)[i] = lv;
}

__global__ void __launch_bounds__(256) wsplit_kernel(
    const float* __restrict__ W0, const float* __restrict__ W1,
    const float* __restrict__ W2, const float* __restrict__ W3,
    __nv_bfloat16* H0, __nv_bfloat16* L0, __nv_bfloat16* H1, __nv_bfloat16* L1,
    __nv_bfloat16* H2, __nv_bfloat16* L2, __nv_bfloat16* H3, __nv_bfloat16* L3)
{
    const int z = blockIdx.z;
    const float* W = (z == 0) ? W0 : (z == 1) ? W1 : (z == 2) ? W2 : W3;
    __nv_bfloat16* H = (z == 0) ? H0 : (z == 1) ? H1 : (z == 2) ? H2 : H3;
    __nv_bfloat16* L = (z == 0) ? L0 : (z == 1) ? L1 : (z == 2) ? L2 : L3;

    __shared__ float ts[32][33];
    const int n0 = blockIdx.x * 32, k0 = blockIdx.y * 32;
    const int tx = threadIdx.x, ty = threadIdx.y;
#pragma unroll
    for (int r = 0; r < 4; r++)
        ts[ty + 8 * r][tx] = W[(size_t)(k0 + ty + 8 * r) * DMODEL + n0 + tx];
    __syncthreads();
#pragma unroll
    for (int r = 0; r < 4; r++) {
        int n = n0 + ty + 8 * r;
        float a = ts[tx][ty + 8 * r];
        __nv_bfloat16 h = __float2bfloat16_rn(a);
        H[(size_t)n * DMODEL + k0 + tx] = h;
        L[(size_t)n * DMODEL + k0 + tx] = __float2bfloat16_rn(a - __bfloat162float(h));
    }
}

// ---------------- WMMA split-bf16 GEMM (unchanged from R3) ----------------
#define LDM 40

__global__ void __launch_bounds__(256) gemm_wmma(
    const __nv_bfloat16* __restrict__ Ah, const __nv_bfloat16* __restrict__ Al,
    const __nv_bfloat16* __restrict__ Bh0, const __nv_bfloat16* __restrict__ Bl0,
    const __nv_bfloat16* __restrict__ Bh1, const __nv_bfloat16* __restrict__ Bl1,
    const __nv_bfloat16* __restrict__ Bh2, const __nv_bfloat16* __restrict__ Bl2,
    float* C0, float* C1, float* C2)
{
    const int z = blockIdx.z;
    const __nv_bfloat16* Bh = (z == 0) ? Bh0 : (z == 1) ? Bh1 : Bh2;
    const __nv_bfloat16* Bl = (z == 0) ? Bl0 : (z == 1) ? Bl1 : Bl2;
    float* C = (z == 0) ? C0 : (z == 1) ? C1 : C2;

    __shared__ __nv_bfloat16 As[2][128 * LDM];
    __shared__ __nv_bfloat16 Bs[2][128 * LDM];

    const int tid = threadIdx.x;
    const int wid = tid >> 5;
    const int wm = wid & 3;
    const int wn = wid >> 2;
    const int m0 = blockIdx.y * 128;
    const int n0 = blockIdx.x * 128;

    wmma::fragment<wmma::accumulator, 16, 16, 16, float> acc[2][4];
#pragma unroll
    for (int i = 0; i < 2; i++)
#pragma unroll
        for (int j = 0; j < 4; j++) wmma::fill_fragment(acc[i][j], 0.0f);

    const int r  = tid >> 2;
    const int ch = tid & 3;

    for (int kc = 0; kc < DMODEL; kc += 32) {
#pragma unroll
        for (int hf = 0; hf < 2; hf++) {
            const int row = r + hf * 64;
            const size_t go = (size_t)row * DMODEL + kc + ch * 8;
            const int so = row * LDM + ch * 8;
            *reinterpret_cast<uint4*>(&As[0][so]) =
                *reinterpret_cast<const uint4*>(&Ah[(size_t)m0 * DMODEL + go]);
            *reinterpret_cast<uint4*>(&As[1][so]) =
                *reinterpret_cast<const uint4*>(&Al[(size_t)m0 * DMODEL + go]);
            *reinterpret_cast<uint4*>(&Bs[0][so]) =
                *reinterpret_cast<const uint4*>(&Bh[(size_t)n0 * DMODEL + go]);
            *reinterpret_cast<uint4*>(&Bs[1][so]) =
                *reinterpret_cast<const uint4*>(&Bl[(size_t)n0 * DMODEL + go]);
        }
        __syncthreads();

#pragma unroll
        for (int ks = 0; ks < 32; ks += 16) {
            wmma::fragment<wmma::matrix_a, 16, 16, 16, __nv_bfloat16,
                           wmma::row_major> ah[2], al[2];
#pragma unroll
            for (int i = 0; i < 2; i++) {
                wmma::load_matrix_sync(ah[i], &As[0][(wm * 32 + 16 * i) * LDM + ks], LDM);
                wmma::load_matrix_sync(al[i], &As[1][(wm * 32 + 16 * i) * LDM + ks], LDM);
            }
#pragma unroll
            for (int j = 0; j < 4; j++) {
                wmma::fragment<wmma::matrix_b, 16, 16, 16, __nv_bfloat16,
                               wmma::col_major> bh, bl;
                wmma::load_matrix_sync(bh, &Bs[0][(wn * 64 + 16 * j) * LDM + ks], LDM);
                wmma::load_matrix_sync(bl, &Bs[1][(wn * 64 + 16 * j) * LDM + ks], LDM);
#pragma unroll
                for (int i = 0; i < 2; i++) {
                    wmma::mma_sync(acc[i][j], ah[i], bh, acc[i][j]);
                    wmma::mma_sync(acc[i][j], ah[i], bl, acc[i][j]);
                    wmma::mma_sync(acc[i][j], al[i], bh, acc[i][j]);
                }
            }
        }
        __syncthreads();
    }

#pragma unroll
    for (int i = 0; i < 2; i++)
#pragma unroll
        for (int j = 0; j < 4; j++)
            wmma::store_matrix_sync(
                &C[(size_t)(m0 + wm * 32 + 16 * i) * DMODEL + n0 + wn * 64 + 16 * j],
                acc[i][j], DMODEL, wmma::mem_row_major);
}

__global__ void __launch_bounds__(256) bias_add(
    float* __restrict__ out, const float* __restrict__ bo)
{
    int i = blockIdx.x * 256 + threadIdx.x;
    float4 v = reinterpret_cast<float4*>(out)[i];
    float4 b = *reinterpret_cast<const float4*>(&bo[(i * 4) & (DMODEL - 1)]);
    v.x += b.x; v.y += b.y; v.z += b.z; v.w += b.w;
    reinterpret_cast<float4*>(out)[i] = v;
}

// ---------------- mma.sync flash attention (register-resident) ----------------
// CTA = 128 query rows x 1 head, 8 warps, each warp owns 16 rows x all keys.
// S accum, softmax state (m,l), P, and O all live in registers; K/V tiles in
// smem (hi/lo bf16, pitch 72). 2 syncthreads per 64-key tile.
#define LP 72        // bf16 pitch: rows 144B apart -> ldmatrix conflict-free
#define KOFF_H 0
#define KOFF_L 9216
#define VOFF_H 18432
#define VOFF_L 27648
// Q staging aliases the same 36864B region: Qh at 0, Ql at 18432.

__device__ __forceinline__ void ldsm_x4(uint32_t* r, uint32_t addr) {
    asm volatile("ldmatrix.sync.aligned.m8n8.x4.shared.b16 {%0,%1,%2,%3}, [%4];"
        : "=r"(r[0]), "=r"(r[1]), "=r"(r[2]), "=r"(r[3]) : "r"(addr));
}
__device__ __forceinline__ void ldsm_x4_t(uint32_t* r, uint32_t addr) {
    asm volatile("ldmatrix.sync.aligned.m8n8.x4.trans.shared.b16 {%0,%1,%2,%3}, [%4];"
        : "=r"(r[0]), "=r"(r[1]), "=r"(r[2]), "=r"(r[3]) : "r"(addr));
}
__device__ __forceinline__ void mma16816(float* c, const uint32_t* a,
                                         const uint32_t* b) {
    asm volatile("mma.sync.aligned.m16n8k16.row.col.f32.bf16.bf16.f32 "
        "{%0,%1,%2,%3}, {%4,%5,%6,%7}, {%8,%9}, {%0,%1,%2,%3};"
        : "+f"(c[0]), "+f"(c[1]), "+f"(c[2]), "+f"(c[3])
        : "r"(a[0]), "r"(a[1]), "r"(a[2]), "r"(a[3]), "r"(b[0]), "r"(b[1]));
}

__device__ __forceinline__ void split_store4(
    __nv_bfloat16* __restrict__ H, __nv_bfloat16* __restrict__ L,
    int idx, float4 v, float scale)
{
    float a0 = v.x * scale, a1 = v.y * scale, a2 = v.z * scale, a3 = v.w * scale;
    __nv_bfloat16 h0 = __float2bfloat16_rn(a0);
    __nv_bfloat16 h1 = __float2bfloat16_rn(a1);
    __nv_bfloat16 h2 = __float2bfloat16_rn(a2);
    __nv_bfloat16 h3 = __float2bfloat16_rn(a3);
    uint2 hw, lw;
    __nv_bfloat162 p0 = {h0, h1}, p1 = {h2, h3};
    hw.x = *reinterpret_cast<unsigned*>(&p0);
    hw.y = *reinterpret_cast<unsigned*>(&p1);
    lw.x = pk2(a0 - __bfloat162float(h0), a1 - __bfloat162float(h1));
    lw.y = pk2(a2 - __bfloat162float(h2), a3 - __bfloat162float(h3));
    *reinterpret_cast<uint2*>(H + idx) = hw;
    *reinterpret_cast<uint2*>(L + idx) = lw;
}

__device__ __forceinline__ void split_pack(float a, float b,
                                           uint32_t& h, uint32_t& l)
{
    __nv_bfloat16 ha = __float2bfloat16_rn(a);
    __nv_bfloat16 hb = __float2bfloat16_rn(b);
    __nv_bfloat162 hh = {ha, hb};
    h = *reinterpret_cast<unsigned*>(&hh);
    l = pk2(a - __bfloat162float(ha), b - __bfloat162float(hb));
}

__global__ void __launch_bounds__(256) attn_mma(
    const float* __restrict__ qg, const float* __restrict__ kg,
    const float* __restrict__ vg, float* __restrict__ outg)
{
    __shared__ char smc[36864];
    __nv_bfloat16* Kh = reinterpret_cast<__nv_bfloat16*>(smc + KOFF_H);
    __nv_bfloat16* Kl = reinterpret_cast<__nv_bfloat16*>(smc + KOFF_L);
    __nv_bfloat16* Vh = reinterpret_cast<__nv_bfloat16*>(smc + VOFF_H);
    __nv_bfloat16* Vl = reinterpret_cast<__nv_bfloat16*>(smc + VOFF_L);

    const int tid  = threadIdx.x;
    const int w    = tid >> 5;
    const int lane = tid & 31;
    const int h    = blockIdx.y;
    const int ib   = (int)(gridDim.x - 1u - blockIdx.x);  // heavy first
    const int row0 = ib * 128;
    const int hoff = h * DHEAD;
    const uint32_t smb = smem_u32(smc);

    // -------- stage Q (128x64, beta-scaled, hi/lo) through K/V region --------
    {
        __nv_bfloat16* Qh = reinterpret_cast<__nv_bfloat16*>(smc);
        __nv_bfloat16* Ql = reinterpret_cast<__nv_bfloat16*>(smc + 18432);
        const int r  = tid >> 1;
        const int cb = (tid & 1) * 32;
        const float* qp = qg + (size_t)(row0 + r) * DMODEL + hoff + cb;
#pragma unroll
        for (int u = 0; u < 8; u++) {
            float4 v = *reinterpret_cast<const float4*>(qp + 4 * u);
            split_store4(Qh, Ql, r * LP + cb + 4 * u, v, 0.125f);
        }
    }
    __syncthreads();

    // -------- persistent Q A-fragments (16 rows per warp, K=64) --------
    uint32_t qh[4][4], ql[4][4];
    {
        const int qrow = w * 16 + (lane & 15);
        const int csel = (lane >> 4) * 8;
#pragma unroll
        for (int kt = 0; kt < 4; kt++) {
            uint32_t ah = smb + (uint32_t)((qrow * LP + kt * 16 + csel) * 2);
            ldsm_x4(qh[kt], ah);
            ldsm_x4(ql[kt], ah + 18432);
        }
    }
    __syncthreads();

    float o[8][4];
#pragma unroll
    for (int nt = 0; nt < 8; nt++)
#pragma unroll
        for (int j = 0; j < 4; j++) o[nt][j] = 0.f;
    float m0 = -1e30f, m1 = -1e30f, l0 = 0.f, l1 = 0.f;

    const int r0g = row0 + w * 16 + (lane >> 2);  // this thread's first row
    const int jmax = 2 * ib + 1;

    for (int jb = 0; jb <= jmax; jb++) {
        // -------- load K/V tile (64x64), hi/lo split --------
        {
            const int r  = tid >> 2;
            const int cb = (tid & 3) * 16;
            const float* kp = kg + (size_t)(jb * 64 + r) * DMODEL + hoff + cb;
            const float* vp = vg + (size_t)(jb * 64 + r) * DMODEL + hoff + cb;
#pragma unroll
            for (int u = 0; u < 4; u++) {
                float4 kv = *reinterpret_cast<const float4*>(kp + 4 * u);
                float4 vv = *reinterpret_cast<const float4*>(vp + 4 * u);
                split_store4(Kh, Kl, r * LP + cb + 4 * u, kv, 1.0f);
                split_store4(Vh, Vl, r * LP + cb + 4 * u, vv, 1.0f);
            }
        }
        __syncthreads();

        // warp entirely in the future of this key tile? (warp-uniform)
        if (jb * 64 <= row0 + w * 16 + 15) {
            // -------- S = Q.K^T : 16x64 in registers --------
            float c[8][4];
#pragma unroll
            for (int nt = 0; nt < 8; nt++)
#pragma unroll
                for (int j = 0; j < 4; j++) c[nt][j] = 0.f;

            const int kkey = (lane >> 4) * 8 + (lane & 7);
            const int kcol = ((lane >> 3) & 1) * 8;
#pragma unroll
            for (int kt = 0; kt < 4; kt++) {
#pragma unroll
                for (int ntp = 0; ntp < 4; ntp++) {
                    uint32_t bh[4], bl[4];
                    uint32_t ka = smb + (uint32_t)(((ntp * 16 + kkey) * LP +
                                                   kt * 16 + kcol) * 2);
                    ldsm_x4(bh, ka + KOFF_H);
                    ldsm_x4(bl, ka + KOFF_L);
                    mma16816(c[2 * ntp],     qh[kt], bh);
                    mma16816(c[2 * ntp],     qh[kt], bl);
                    mma16816(c[2 * ntp],     ql[kt], bh);
                    mma16816(c[2 * ntp + 1], qh[kt], bh + 2);
                    mma16816(c[2 * ntp + 1], qh[kt], bl + 2);
                    mma16816(c[2 * ntp + 1], ql[kt], bh + 2);
                }
            }

            // -------- causal mask (only near/on diagonal) --------
            if (jb >= 2 * ib) {
#pragma unroll
                for (int nt = 0; nt < 8; nt++) {
                    int colg = jb * 64 + nt * 8 + 2 * (lane & 3);
                    if (colg     > r0g)     c[nt][0] = -1e30f;
                    if (colg + 1 > r0g)     c[nt][1] = -1e30f;
                    if (colg     > r0g + 8) c[nt][2] = -1e30f;
                    if (colg + 1 > r0g + 8) c[nt][3] = -1e30f;
                }
            }

            // -------- register online softmax (rows r0g, r0g+8) --------
            float mx0 = -1e30f, mx1 = -1e30f;
#pragma unroll
            for (int nt = 0; nt < 8; nt++) {
                mx0 = fmaxf(mx0, fmaxf(c[nt][0], c[nt][1]));
                mx1 = fmaxf(mx1, fmaxf(c[nt][2], c[nt][3]));
            }
            mx0 = fmaxf(mx0, __shfl_xor_sync(0xffffffffu, mx0, 1));
            mx0 = fmaxf(mx0, __shfl_xor_sync(0xffffffffu, mx0, 2));
            mx1 = fmaxf(mx1, __shfl_xor_sync(0xffffffffu, mx1, 1));
            mx1 = fmaxf(mx1, __shfl_xor_sync(0xffffffffu, mx1, 2));
            float mn0 = fmaxf(m0, mx0), mn1 = fmaxf(m1, mx1);
            float sc0 = __expf(m0 - mn0), sc1 = __expf(m1 - mn1);
            m0 = mn0; m1 = mn1;
            float s0 = 0.f, s1 = 0.f;
#pragma unroll
            for (int nt = 0; nt < 8; nt++) {
                c[nt][0] = __expf(c[nt][0] - mn0); s0 += c[nt][0];
                c[nt][1] = __expf(c[nt][1] - mn0); s0 += c[nt][1];
                c[nt][2] = __expf(c[nt][2] - mn1); s1 += c[nt][2];
                c[nt][3] = __expf(c[nt][3] - mn1); s1 += c[nt][3];
            }
            s0 += __shfl_xor_sync(0xffffffffu, s0, 1);
            s0 += __shfl_xor_sync(0xffffffffu, s0, 2);
            s1 += __shfl_xor_sync(0xffffffffu, s1, 1);
            s1 += __shfl_xor_sync(0xffffffffu, s1, 2);
            l0 = l0 * sc0 + s0;
            l1 = l1 * sc1 + s1;
#pragma unroll
            for (int nt = 0; nt < 8; nt++) {
                o[nt][0] *= sc0; o[nt][1] *= sc0;
                o[nt][2] *= sc1; o[nt][3] *= sc1;
            }

            // -------- P -> A-fragments (register reuse, hi/lo) --------
            uint32_t ph[4][4], pl[4][4];
#pragma unroll
            for (int kt = 0; kt < 4; kt++) {
                split_pack(c[2 * kt][0],     c[2 * kt][1],     ph[kt][0], pl[kt][0]);
                split_pack(c[2 * kt][2],     c[2 * kt][3],     ph[kt][1], pl[kt][1]);
                split_pack(c[2 * kt + 1][0], c[2 * kt + 1][1], ph[kt][2], pl[kt][2]);
                split_pack(c[2 * kt + 1][2], c[2 * kt + 1][3], ph[kt][3], pl[kt][3]);
            }

            // -------- O += P.V --------
            const int vkey = ((lane >> 3) & 1) * 8 + (lane & 7);
            const int vcol = (lane >> 4) * 8;
#pragma unroll
            for (int ntp = 0; ntp < 4; ntp++) {
#pragma unroll
                for (int kt = 0; kt < 4; kt++) {
                    uint32_t vh[4], vl[4];
                    uint32_t va = smb + (uint32_t)(((kt * 16 + vkey) * LP +
                                                   ntp * 16 + vcol) * 2);
                    ldsm_x4_t(vh, va + VOFF_H);
                    ldsm_x4_t(vl, va + VOFF_L);
                    mma16816(o[2 * ntp],     ph[kt], vh);
                    mma16816(o[2 * ntp],     ph[kt], vl);
                    mma16816(o[2 * ntp],     pl[kt], vh);
                    mma16816(o[2 * ntp + 1], ph[kt], vh + 2);
                    mma16816(o[2 * ntp + 1], ph[kt], vl + 2);
                    mma16816(o[2 * ntp + 1], pl[kt], vh + 2);
                }
            }
        }
        __syncthreads();
    }

    // -------- normalize + store --------
    {
        float inv0 = 1.0f / l0, inv1 = 1.0f / l1;
        const int cbase = hoff + 2 * (lane & 3);
        float* d0 = outg + (size_t)r0g * DMODEL;
        float* d1 = outg + (size_t)(r0g + 8) * DMODEL;
#pragma unroll
        for (int nt = 0; nt < 8; nt++) {
            float2 v0 = make_float2(o[nt][0] * inv0, o[nt][1] * inv0);
            float2 v1 = make_float2(o[nt][2] * inv1, o[nt][3] * inv1);
            *reinterpret_cast<float2*>(d0 + cbase + nt * 8) = v0;
            *reinterpret_cast<float2*>(d1 + cbase + nt * 8) = v1;
        }
    }
}

// ---------------------------------------------------------------------------
extern "C" void kernel_launch(void* const* d_in, const int* in_sizes, int n_in,
                              void* d_out, int out_size)
{
    const float* x  = (const float*)d_in[0];
    const float* Wq = (const float*)d_in[1];
    const float* Wk = (const float*)d_in[2];
    const float* Wv = (const float*)d_in[3];
    const float* Wo = (const float*)d_in[4];
    const float* bo = (const float*)d_in[5];
    float* out = (float*)d_out;

    float *q, *k, *v, *at;
    __nv_bfloat16 *xh, *xl, *ath, *atl;
    __nv_bfloat16 *wqh, *wql, *wkh, *wkl, *wvh, *wvl, *woh, *wol;
    cudaGetSymbolAddress((void**)&q,  g_q);
    cudaGetSymbolAddress((void**)&k,  g_k);
    cudaGetSymbolAddress((void**)&v,  g_v);
    cudaGetSymbolAddress((void**)&at, g_at);
    cudaGetSymbolAddress((void**)&xh,  g_xh);
    cudaGetSymbolAddress((void**)&xl,  g_xl);
    cudaGetSymbolAddress((void**)&ath, g_ath);
    cudaGetSymbolAddress((void**)&atl, g_atl);
    cudaGetSymbolAddress((void**)&wqh, g_wqh);
    cudaGetSymbolAddress((void**)&wql, g_wql);
    cudaGetSymbolAddress((void**)&wkh, g_wkh);
    cudaGetSymbolAddress((void**)&wkl, g_wkl);
    cudaGetSymbolAddress((void**)&wvh, g_wvh);
    cudaGetSymbolAddress((void**)&wvl, g_wvl);
    cudaGetSymbolAddress((void**)&woh, g_woh);
    cudaGetSymbolAddress((void**)&wol, g_wol);

    // prep: split x, transpose+split all weights
    split_kernel<<<SEQ * DMODEL / 1024, 256>>>(x, xh, xl);
    dim3 gw(DMODEL / 32, DMODEL / 32, 4);
    wsplit_kernel<<<gw, dim3(32, 8)>>>(Wq, Wk, Wv, Wo,
        wqh, wql, wkh, wkl, wvh, wvl, woh, wol);

    // QKV projections (tensor cores)
    dim3 g1(DMODEL / 128, SEQ / 128, 3);
    gemm_wmma<<<g1, 256>>>(xh, xl,
        wqh, wql, wkh, wkl, wvh, wvl, q, k, v);

    // causal flash attention (mma.sync, register-resident)
    dim3 g2(SEQ / 128, HEADS);
    attn_mma<<<g2, 256>>>(q, k, v, at);

    // split attention output, then Wo projection
    split_kernel<<<SEQ * DMODEL / 1024, 256>>>(at, ath, atl);
    dim3 g3(DMODEL / 128, SEQ / 128, 1);
    gemm_wmma<<<g3, 256>>>(ath, atl,
        woh, wol, woh, wol, woh, wol, out, out, out);

    // bias epilogue
    bias_add<<<SEQ * DMODEL / 1024, 256>>>(out, bo);
}